// round 9
// baseline (speedup 1.0000x reference)
#include <cuda.h>
#include <cuda_runtime.h>
#include <math.h>

#define T      128
#define F      512
#define H      1024
#define RZ     1536
#define CPB    8
#define NC     128           // compute CTAs
#define NPF    20            // L2-prefetch CTAs
#define NTH    288           // 256 consumers + 1 TMA warp
#define D      4
#define LOOKAHEAD 12
#define SLOT_BYTES (RZ * CPB * 4)     // 49152
#define SLOT_WORDS (RZ * CPB)
#define STEP_LINES (RZ * H * 4 / 128)
#define SMEM_TOTAL (D * SLOT_BYTES + 512)

__device__ float    g_h[T * H];
__device__ unsigned g_cnt[T];

__global__ void pg_init() {
    if (threadIdx.x < T) g_cnt[threadIdx.x] = 0u;
}

__device__ __forceinline__ unsigned ld_acq(const unsigned* p) {
    unsigned v;
    asm volatile("ld.global.acquire.gpu.u32 %0, [%1];" : "=r"(v) : "l"(p) : "memory");
    return v;
}
__device__ __forceinline__ void red_rel(unsigned* p, unsigned v) {
    asm volatile("red.release.gpu.global.add.u32 [%0], %1;" :: "l"(p), "r"(v) : "memory");
}
__device__ __forceinline__ int ld_acq_sh(unsigned addr) {
    int v;
    asm volatile("ld.acquire.cta.shared.s32 %0, [%1];" : "=r"(v) : "r"(addr) : "memory");
    return v;
}
__device__ __forceinline__ void st_rel_sh(unsigned addr, int v) {
    asm volatile("st.release.cta.shared.s32 [%0], %1;" :: "r"(addr), "r"(v) : "memory");
}
__device__ __forceinline__ void prefetch_l2(const void* p) {
    asm volatile("prefetch.global.L2 [%0];" :: "l"(p));
}
__device__ __forceinline__ void bar1() {     // consumers only (256 threads)
    asm volatile("bar.sync 1, 256;" ::: "memory");
}
__device__ __forceinline__ void mbar_init(unsigned a, unsigned cnt) {
    asm volatile("mbarrier.init.shared.b64 [%0], %1;" :: "r"(a), "r"(cnt) : "memory");
}
__device__ __forceinline__ void mbar_expect_tx(unsigned a, unsigned bytes) {
    asm volatile("mbarrier.arrive.expect_tx.shared.b64 _, [%0], %1;"
                 :: "r"(a), "r"(bytes) : "memory");
}
__device__ __forceinline__ void mbar_wait(unsigned a, unsigned parity) {
    unsigned done;
    asm volatile(
        "{\n\t.reg .pred p;\n\t"
        "mbarrier.try_wait.parity.acquire.cta.shared::cta.b64 p, [%1], %2;\n\t"
        "selp.b32 %0, 1, 0, p;\n\t}"
        : "=r"(done) : "r"(a), "r"(parity) : "memory");
    if (!done) {
        asm volatile(
            "{\n\t.reg .pred P1;\n\t"
            "WL_%=:\n\t"
            "mbarrier.try_wait.parity.acquire.cta.shared::cta.b64 P1, [%0], %1, 0x989680;\n\t"
            "@P1 bra.uni WD_%=;\n\t"
            "bra.uni WL_%=;\n\t"
            "WD_%=:\n\t}"
            :: "r"(a), "r"(parity) : "memory");
    }
}
__device__ __forceinline__ void tma_load3d(unsigned smem, const CUtensorMap* m,
                                           int cx, int cy, int cz, unsigned mbar) {
    asm volatile(
        "cp.async.bulk.tensor.3d.shared::cta.global.tile.mbarrier::complete_tx::bytes "
        "[%0], [%1, {%2, %3, %4}], [%5];"
        :: "r"(smem), "l"(m), "r"(cx), "r"(cy), "r"(cz), "r"(mbar) : "memory");
}

__global__ void __launch_bounds__(NTH, 1) pg_fused(
    const __grid_constant__ CUtensorMap tmap,
    const float* __restrict__ x,    // (1, T, F)
    const float* __restrict__ h0,   // (H,)
    const float* __restrict__ Ws,   // (T, RZ, H)  (raw ptr: prefetch CTAs only)
    const float* __restrict__ bs,   // (T, H)
    const float* __restrict__ Wo,   // (H, 2)
    const float* __restrict__ bo,   // (2,)
    float* __restrict__ out)        // [actors(2), h_final(H)]
{
    extern __shared__ char sm[];
    const int tid = threadIdx.x;

    // ================= L2-prefetch CTAs =================
    if (blockIdx.x >= NC) {
        const int p  = blockIdx.x - NC;
        const int gt = p * NTH + tid;
        for (int t = 0; t < T; ++t) {
            if (t >= LOOKAHEAD) {
                if (tid == 0) {
                    while (ld_acq(&g_cnt[t - LOOKAHEAD]) != (unsigned)NC) { }
                }
                __syncthreads();
            }
            const char* base = (const char*)(Ws + (size_t)t * RZ * H);
            for (int line = gt; line < STEP_LINES; line += NPF * NTH)
                prefetch_l2(base + (size_t)line * 128);
        }
        return;
    }

    // ================= compute CTAs =================
    // smem: D tiles (rows contiguous, 32B per row), then s_red, mbarriers, consumed
    float* s_w   = (float*)sm;                          // D * 12288 floats
    float* s_red = (float*)(sm + D * SLOT_BYTES);       // 64 floats
    unsigned long long* s_mbar = (unsigned long long*)(s_red + 64);  // D, 8B aligned
    int* s_consumed = (int*)(s_mbar + D);

    const int cg = blockIdx.x;
    unsigned sbase = (unsigned)__cvta_generic_to_shared(s_w);
    unsigned mbase = (unsigned)__cvta_generic_to_shared(s_mbar);
    unsigned cons  = (unsigned)__cvta_generic_to_shared(s_consumed);

    if (tid == 0) {
        for (int i = 0; i < D; ++i) mbar_init(mbase + i * 8, 1u);
        *s_consumed = 0;
    }
    __syncthreads();

    if (tid >= 256) {
        // ---------------- TMA producer (single thread) ----------------
        if (tid == 256) {
            for (int t = 0; t < T; ++t) {
                while (ld_acq_sh(cons) < t - (D - 1)) { }
                const int slot = t % D;
                unsigned mb = mbase + slot * 8;
                unsigned sb = sbase + slot * SLOT_BYTES;
                mbar_expect_tx(mb, (unsigned)SLOT_BYTES);
#pragma unroll
                for (int b = 0; b < 6; ++b)
                    tma_load3d(sb + b * (256 * 32), &tmap, cg * CPB, b * 256, t, mb);
            }
        }
        return;
    }

    // ---------------- consumers ----------------
    const int w  = tid >> 5;                // 0..7 : 192 rows each
    const int l  = tid & 31;
    const int rp = l >> 1;                  // row-pair index 0..15
    const int hh = l & 1;                   // col half 0/1
    const int nx = (w < 3) ? ((512 - w * 192) / 16 < 12 ? (512 - w * 192) / 16 : 12) : 0;
    // nx: number of 16-row groups from x (w0:12, w1:12, w2:8, else 0)

    for (int t = 0; t < T; ++t) {
        const int slot = t % D;
        float bval = 0.f;
        if (tid < 8) bval = __ldg(&bs[t * H + cg * CPB + tid]);

        mbar_wait(mbase + slot * 8, (unsigned)((t / D) & 1));   // tile ready

        const float* wslot = s_w + slot * SLOT_WORDS;
        float4 wv[12];
        float acc0 = 0.f, acc1 = 0.f, acc2 = 0.f, acc3 = 0.f;

        // Load all 12 weight float4s (conflict-free: 16 rows x 2 halves per instr)
#pragma unroll
        for (int i = 0; i < 12; ++i) {
            int row = w * 192 + 16 * i + rp;
            wv[i] = *(const float4*)(wslot + row * 8 + hh * 4);
        }
        // x-part FMAs (rows < 512): hides the h poll below
#pragma unroll
        for (int i = 0; i < 12; ++i) {
            if (i < nx) {
                int row = w * 192 + 16 * i + rp;
                float zv = __ldg(&x[t * F + row]);
                acc0 = fmaf(zv, wv[i].x, acc0); acc1 = fmaf(zv, wv[i].y, acc1);
                acc2 = fmaf(zv, wv[i].z, acc2); acc3 = fmaf(zv, wv[i].w, acc3);
            }
        }

        // acquire h_{t-1}
        if (tid == 0 && t > 0) {
            while (ld_acq(&g_cnt[t - 1]) != (unsigned)NC) { }
        }
        bar1();

        const float* hp = (t == 0) ? h0 : (g_h + (size_t)(t - 1) * H);
#pragma unroll
        for (int i = 0; i < 12; ++i) {
            if (i >= nx) {
                int row = w * 192 + 16 * i + rp;
                float zv = hp[row - F];
                acc0 = fmaf(zv, wv[i].x, acc0); acc1 = fmaf(zv, wv[i].y, acc1);
                acc2 = fmaf(zv, wv[i].z, acc2); acc3 = fmaf(zv, wv[i].w, acc3);
            }
        }

        // reduce over the 16 row-pair lanes (keep bit0 = col half)
#pragma unroll
        for (int off = 2; off <= 16; off <<= 1) {
            acc0 += __shfl_xor_sync(0xffffffffu, acc0, off);
            acc1 += __shfl_xor_sync(0xffffffffu, acc1, off);
            acc2 += __shfl_xor_sync(0xffffffffu, acc2, off);
            acc3 += __shfl_xor_sync(0xffffffffu, acc3, off);
        }
        if (l < 2) {
            float4 v = make_float4(acc0, acc1, acc2, acc3);
            *(float4*)(s_red + w * 8 + l * 4) = v;
        }
        bar1();                              // slot fully consumed

        if (tid == 0) st_rel_sh(cons, t + 1);   // recycle slot for TMA
        if (tid < 8) {
            float s = bval;
#pragma unroll
            for (int ww = 0; ww < 8; ++ww) s += s_red[ww * 8 + tid];
            float hv = tanhf(s);
            int col = cg * CPB + tid;
            g_h[(size_t)t * H + col] = hv;
            if (t == T - 1) out[2 + col] = hv;
        }
        __syncwarp(0xffffffffu);
        if (tid == 0) red_rel(&g_cnt[t], 1u);
    }

    // ---------------- actor head (CTA 0) ----------------
    if (cg == 0) {
        if (tid == 0) while (ld_acq(&g_cnt[T - 1]) != (unsigned)NC) { }
        bar1();
        const float* hf = g_h + (size_t)(T - 1) * H;
        float r0 = 0.f, r1 = 0.f;
        for (int i = tid; i < H; i += 256) {
            float hv = hf[i];
            r0 = fmaf(hv, Wo[2 * i + 0], r0);
            r1 = fmaf(hv, Wo[2 * i + 1], r1);
        }
#pragma unroll
        for (int off = 16; off >= 1; off >>= 1) {
            r0 += __shfl_xor_sync(0xffffffffu, r0, off);
            r1 += __shfl_xor_sync(0xffffffffu, r1, off);
        }
        if (l == 0) { s_red[w] = r0; s_red[8 + w] = r1; }
        bar1();
        if (tid == 0) {
            float s0 = 0.f, s1 = 0.f;
#pragma unroll
            for (int ww = 0; ww < 8; ++ww) { s0 += s_red[ww]; s1 += s_red[8 + ww]; }
            out[0] = s0 + bo[0];
            out[1] = s1 + bo[1];
        }
    }
}

typedef CUresult (*pg_enc_t)(CUtensorMap*, CUtensorMapDataType, cuuint32_t, void*,
                             const cuuint64_t*, const cuuint64_t*, const cuuint32_t*,
                             const cuuint32_t*, CUtensorMapInterleave, CUtensorMapSwizzle,
                             CUtensorMapL2promotion, CUtensorMapFloatOOBfill);

extern "C" void kernel_launch(void* const* d_in, const int* in_sizes, int n_in,
                              void* d_out, int out_size) {
    const float* x  = (const float*)d_in[0];
    const float* h0 = (const float*)d_in[1];
    const float* Ws = (const float*)d_in[2];
    const float* bs = (const float*)d_in[3];
    const float* Wo = (const float*)d_in[4];
    const float* bo = (const float*)d_in[5];
    float* out = (float*)d_out;

    static pg_enc_t enc = nullptr;
    static bool init_done = false;
    if (!init_done) {
        cudaFuncSetAttribute(pg_fused, cudaFuncAttributeMaxDynamicSharedMemorySize,
                             SMEM_TOTAL);
        void* fn = nullptr;
        cudaDriverEntryPointQueryResult qr;
        cudaGetDriverEntryPoint("cuTensorMapEncodeTiled", &fn, cudaEnableDefault, &qr);
        enc = (pg_enc_t)fn;
        init_done = true;
    }

    CUtensorMap tmap;
    cuuint64_t dims[3]    = {H, RZ, T};
    cuuint64_t strides[2] = {H * 4ull, (cuuint64_t)RZ * H * 4ull};
    cuuint32_t box[3]     = {CPB, 256, 1};
    cuuint32_t es[3]      = {1, 1, 1};
    enc(&tmap, CU_TENSOR_MAP_DATA_TYPE_FLOAT32, 3, (void*)Ws,
        dims, strides, box, es,
        CU_TENSOR_MAP_INTERLEAVE_NONE, CU_TENSOR_MAP_SWIZZLE_NONE,
        CU_TENSOR_MAP_L2_PROMOTION_L2_128B, CU_TENSOR_MAP_FLOAT_OOB_FILL_NONE);

    pg_init<<<1, 128>>>();
    pg_fused<<<NC + NPF, NTH, SMEM_TOTAL>>>(tmap, x, h0, Ws, bs, Wo, bo, out);
}

// round 10
// speedup vs baseline: 1.2521x; 1.2521x over previous
#include <cuda_runtime.h>
#include <math.h>

#define T      128
#define F      512
#define H      1024
#define RZ     1536
#define CPB    8
#define NC     128           // compute CTAs
#define NPF    20            // L2-prefetch CTAs
#define NTH    384           // 256 consumers + 128 producers
#define D      4
#define LOOKAHEAD 12
#define SLOT_BYTES (RZ * CPB * 4)     // 49152
#define SLOT_WORDS (RZ * CPB)
#define STEP_LINES (RZ * H * 4 / 128)

__device__ float    g_h[T * H];
__device__ unsigned g_cnt[T];

__global__ void pg_init() {
    if (threadIdx.x < T) g_cnt[threadIdx.x] = 0u;
}

__device__ __forceinline__ unsigned ld_acq(const unsigned* p) {
    unsigned v;
    asm volatile("ld.global.acquire.gpu.u32 %0, [%1];" : "=r"(v) : "l"(p) : "memory");
    return v;
}
__device__ __forceinline__ void red_rel(unsigned* p, unsigned v) {
    asm volatile("red.release.gpu.global.add.u32 [%0], %1;" :: "l"(p), "r"(v) : "memory");
}
__device__ __forceinline__ void prefetch_l2(const void* p) {
    asm volatile("prefetch.global.L2 [%0];" :: "l"(p));
}
__device__ __forceinline__ void cp_async16(unsigned saddr, const void* gaddr) {
    asm volatile("cp.async.cg.shared.global [%0], [%1], 16;" :: "r"(saddr), "l"(gaddr));
}
__device__ __forceinline__ void cp_commit() { asm volatile("cp.async.commit_group;"); }
template<int N> __device__ __forceinline__ void cp_waitg() {
    asm volatile("cp.async.wait_group %0;" :: "n"(N));
}
__device__ __forceinline__ void bar1() {     // consumers only (256 threads)
    asm volatile("bar.sync 1, 256;" ::: "memory");
}

__global__ void __launch_bounds__(NTH, 1) pg_fused(
    const float* __restrict__ x,    // (1, T, F)
    const float* __restrict__ h0,   // (H,)
    const float* __restrict__ Ws,   // (T, RZ, H)
    const float* __restrict__ bs,   // (T, H)
    const float* __restrict__ Wo,   // (H, 2)
    const float* __restrict__ bo,   // (2,)
    float* __restrict__ out)        // [actors(2), h_final(H)]
{
    extern __shared__ char sm[];
    const int tid = threadIdx.x;

    // ================= L2-prefetch CTAs =================
    if (blockIdx.x >= NC) {
        const int p  = blockIdx.x - NC;
        const int gt = p * NTH + tid;
        for (int t = 0; t < T; ++t) {
            if (t >= LOOKAHEAD) {
                if (tid == 0) {
                    while (ld_acq(&g_cnt[t - LOOKAHEAD]) != (unsigned)NC) { }
                }
                __syncthreads();
            }
            const char* base = (const char*)(Ws + (size_t)t * RZ * H);
            for (int line = gt; line < STEP_LINES; line += NPF * NTH)
                prefetch_l2(base + (size_t)line * 128);
        }
        return;
    }

    // ================= compute CTAs =================
    float* s_w    = (float*)sm;                        // D x 48KB z-tiles
    float* s_red  = (float*)(sm + D * SLOT_BYTES);     // 64
    int*   s_full = (int*)(s_red + 64);                // D
    volatile int* s_consumed = (volatile int*)(s_full + D);

    const int cg = blockIdx.x;
    unsigned sbase = (unsigned)__cvta_generic_to_shared(s_w);

    if (tid == 0) {
        for (int i = 0; i < D; ++i) s_full[i] = 0;
        *s_consumed = 0;
    }
    __syncthreads();

    if (tid >= 256) {
        // ---------------- producers: stream full z-tiles ----------------
        const int pt = tid - 256;                      // 0..127
        const float* gcols = Ws + (size_t)cg * CPB;
        for (int t = 0; t < T; ++t) {
            while (*s_consumed < t - (D - 1)) { }
            unsigned sb = sbase + (unsigned)(t % D) * SLOT_BYTES;
            const float* gb = gcols + (size_t)t * RZ * H;
#pragma unroll
            for (int i = 0; i < 24; ++i) {
                int n   = i * 128 + pt;
                int row = n >> 1;
                int cc  = n & 1;
                unsigned soff = sb + (unsigned)(row * 32 + ((cc ^ ((row >> 2) & 1)) << 4));
                cp_async16(soff, (const void*)(gb + (size_t)row * H + cc * 4));
            }
            cp_commit();
            if (t >= 2) {
                cp_waitg<2>();
                __threadfence_block();
                atomicAdd(&s_full[(t - 2) % D], 1);
            }
        }
        cp_waitg<1>(); __threadfence_block(); atomicAdd(&s_full[(T - 2) % D], 1);
        cp_waitg<0>(); __threadfence_block(); atomicAdd(&s_full[(T - 1) % D], 1);
    } else {
        // ---------------- consumers ----------------
        const int w = tid >> 5, l = tid & 31;
        float xacc[8];

        // ---- prologue: x-part of step 0 (off-chain) ----
        {
            if (tid == 0) {
                while (((volatile int*)s_full)[0] != 128) { }
            }
            bar1();
            const float* wslot = s_w;
#pragma unroll
            for (int j = 0; j < 8; ++j) xacc[j] = 0.f;
#pragma unroll
            for (int i = 0; i < 2; ++i) {
                int r = w * 64 + i * 32 + l;
                float zv = __ldg(&x[r]);
                int sw = (r >> 2) & 1;
                float4 c0 = *(const float4*)(wslot + r * 8 + sw * 4);
                float4 c1 = *(const float4*)(wslot + r * 8 + (sw ^ 1) * 4);
                xacc[0] = fmaf(zv, c0.x, xacc[0]); xacc[1] = fmaf(zv, c0.y, xacc[1]);
                xacc[2] = fmaf(zv, c0.z, xacc[2]); xacc[3] = fmaf(zv, c0.w, xacc[3]);
                xacc[4] = fmaf(zv, c1.x, xacc[4]); xacc[5] = fmaf(zv, c1.y, xacc[5]);
                xacc[6] = fmaf(zv, c1.z, xacc[6]); xacc[7] = fmaf(zv, c1.w, xacc[7]);
            }
        }

        for (int t = 0; t < T; ++t) {
            const int slot = t % D;
            float bval = 0.f;
            if (tid < 8) bval = __ldg(&bs[t * H + cg * CPB + tid]);

            // ---- CRITICAL CHAIN: acquire h_{t-1}, h-part only ----
            if (tid == 0 && t > 0) {
                while (ld_acq(&g_cnt[t - 1]) != (unsigned)NC) { }
            }
            bar1();

            const float* wslot = s_w + slot * SLOT_WORDS;
            const float* hp = (t == 0) ? h0 : (g_h + (size_t)(t - 1) * H);
            float acc[8];
#pragma unroll
            for (int j = 0; j < 8; ++j) acc[j] = xacc[j];

            float zv2[4];
#pragma unroll
            for (int i = 0; i < 4; ++i)                 // issue all 4 LDGs first
                zv2[i] = hp[w * 128 + i * 32 + l];
#pragma unroll
            for (int i = 0; i < 4; ++i) {
                int r = F + w * 128 + i * 32 + l;
                int sw = (r >> 2) & 1;
                float4 c0 = *(const float4*)(wslot + r * 8 + sw * 4);
                float4 c1 = *(const float4*)(wslot + r * 8 + (sw ^ 1) * 4);
                float zv = zv2[i];
                acc[0] = fmaf(zv, c0.x, acc[0]); acc[1] = fmaf(zv, c0.y, acc[1]);
                acc[2] = fmaf(zv, c0.z, acc[2]); acc[3] = fmaf(zv, c0.w, acc[3]);
                acc[4] = fmaf(zv, c1.x, acc[4]); acc[5] = fmaf(zv, c1.y, acc[5]);
                acc[6] = fmaf(zv, c1.z, acc[6]); acc[7] = fmaf(zv, c1.w, acc[7]);
            }

            // ---- reduce over 32 lanes per warp ----
#pragma unroll
            for (int off = 16; off >= 1; off >>= 1)
#pragma unroll
                for (int j = 0; j < 8; ++j)
                    acc[j] += __shfl_xor_sync(0xffffffffu, acc[j], off);
            if (l == 0) {
#pragma unroll
                for (int j = 0; j < 8; ++j) s_red[w * 8 + j] = acc[j];
            }
            bar1();                                   // slot t fully consumed

            if (tid == 0) {                           // recycle slot t
                s_full[slot] = 0;
                __threadfence_block();
                *s_consumed = t + 1;
            }
            if (tid < 8) {                            // finish + publish
                float s = bval;
#pragma unroll
                for (int ww = 0; ww < 8; ++ww) s += s_red[ww * 8 + tid];
                float hv = tanhf(s);
                int col = cg * CPB + tid;
                g_h[(size_t)t * H + col] = hv;
                if (t == T - 1) out[2 + col] = hv;
            }
            __syncwarp(0xffffffffu);
            if (tid == 0) red_rel(&g_cnt[t], 1u);
            // ---- END CRITICAL CHAIN ----

            // ---- x-part of step t+1 (hidden in other CTAs' detect window) ----
            if (t + 1 < T) {
                const int nslot = (t + 1) % D;
                if (tid == 0) {
                    while (((volatile int*)s_full)[nslot] != 128) { }
                }
                bar1();
                const float* wn = s_w + nslot * SLOT_WORDS;
#pragma unroll
                for (int j = 0; j < 8; ++j) xacc[j] = 0.f;
#pragma unroll
                for (int i = 0; i < 2; ++i) {
                    int r = w * 64 + i * 32 + l;
                    float zv = __ldg(&x[(t + 1) * F + r]);
                    int sw = (r >> 2) & 1;
                    float4 c0 = *(const float4*)(wn + r * 8 + sw * 4);
                    float4 c1 = *(const float4*)(wn + r * 8 + (sw ^ 1) * 4);
                    xacc[0] = fmaf(zv, c0.x, xacc[0]); xacc[1] = fmaf(zv, c0.y, xacc[1]);
                    xacc[2] = fmaf(zv, c0.z, xacc[2]); xacc[3] = fmaf(zv, c0.w, xacc[3]);
                    xacc[4] = fmaf(zv, c1.x, xacc[4]); xacc[5] = fmaf(zv, c1.y, xacc[5]);
                    xacc[6] = fmaf(zv, c1.z, xacc[6]); xacc[7] = fmaf(zv, c1.w, xacc[7]);
                }
            }
        }

        // ---------------- actor head (CTA 0) ----------------
        if (cg == 0) {
            if (tid == 0) while (ld_acq(&g_cnt[T - 1]) != (unsigned)NC) { }
            bar1();
            const float* hf = g_h + (size_t)(T - 1) * H;
            float r0 = 0.f, r1 = 0.f;
            for (int i = tid; i < H; i += 256) {
                float hv = hf[i];
                r0 = fmaf(hv, Wo[2 * i + 0], r0);
                r1 = fmaf(hv, Wo[2 * i + 1], r1);
            }
#pragma unroll
            for (int off = 16; off >= 1; off >>= 1) {
                r0 += __shfl_xor_sync(0xffffffffu, r0, off);
                r1 += __shfl_xor_sync(0xffffffffu, r1, off);
            }
            if (l == 0) { s_red[w] = r0; s_red[8 + w] = r1; }
            bar1();
            if (tid == 0) {
                float s0 = 0.f, s1 = 0.f;
#pragma unroll
                for (int ww = 0; ww < 8; ++ww) { s0 += s_red[ww]; s1 += s_red[8 + ww]; }
                out[0] = s0 + bo[0];
                out[1] = s1 + bo[1];
            }
        }
    }
}

extern "C" void kernel_launch(void* const* d_in, const int* in_sizes, int n_in,
                              void* d_out, int out_size) {
    const float* x  = (const float*)d_in[0];
    const float* h0 = (const float*)d_in[1];
    const float* Ws = (const float*)d_in[2];
    const float* bs = (const float*)d_in[3];
    const float* Wo = (const float*)d_in[4];
    const float* bo = (const float*)d_in[5];
    float* out = (float*)d_out;

    static bool attr_set = false;
    if (!attr_set) {
        cudaFuncSetAttribute(pg_fused, cudaFuncAttributeMaxDynamicSharedMemorySize,
                             D * SLOT_BYTES + 1024);
        attr_set = true;
    }

    pg_init<<<1, 128>>>();
    pg_fused<<<NC + NPF, NTH, D * SLOT_BYTES + 1024>>>(x, h0, Ws, bs, Wo, bo, out);
}